// round 3
// baseline (speedup 1.0000x reference)
#include <cuda_runtime.h>

// LiftSplatBEV — fixed shapes
// feat_bn   : [12, 64, 112, 200] f32
// depth_prob: [12, 64, 112, 200] f32
// I_inv     : [2, 6, 3, 3] f32
// E_inv     : [2, 6, 4, 4] f32
// V         : [3, 3] f32
// feat_hw   : [2] i32 (unused, constants hardcoded)
// n         : scalar i32 (unused, =6)
// out       : [2, 64, 200, 200] f32

static constexpr int B_   = 2;
static constexpr int N_   = 6;
static constexpr int C_   = 64;
static constexpr int HF_  = 112;
static constexpr int WF_  = 200;
static constexpr int D_   = 64;
static constexpr int HWP  = HF_ * WF_;     // 22400
static constexpr int BEVH = 200;
static constexpr int BEVW = 200;
static constexpr int HWB  = BEVH * BEVW;   // 40000

// Accumulator scratch: [b][bev_cell][channel]  (channel contiguous -> v4 atomics)
__device__ float g_scratch[(size_t)B_ * HWB * C_];

__global__ void k_zero() {
    const int n4 = (B_ * HWB * C_) / 4;
    float4 z = make_float4(0.f, 0.f, 0.f, 0.f);
    float4* p = reinterpret_cast<float4*>(g_scratch);
    for (int i = blockIdx.x * blockDim.x + threadIdx.x; i < n4;
         i += gridDim.x * blockDim.x)
        p[i] = z;
}

__device__ __forceinline__ void red4(float* a, float4 v) {
    asm volatile("red.global.add.v4.f32 [%0], {%1,%2,%3,%4};"
                 :: "l"(a), "f"(v.x), "f"(v.y), "f"(v.z), "f"(v.w)
                 : "memory");
}

// Scatter one corner's 4-channel contribution. `uni` is warp-uniform.
__device__ __forceinline__ void emit(float* __restrict__ sb, int idx, bool uni,
                                     float w, float4 f, int c) {
    float4 v = make_float4(f.x * w, f.y * w, f.z * w, f.w * w);
    if (uni) {
        // whole warp targets one cell: reduce in-warp, single atomic
        #pragma unroll
        for (int o = 16; o > 0; o >>= 1) {
            v.x += __shfl_xor_sync(0xffffffffu, v.x, o);
            v.y += __shfl_xor_sync(0xffffffffu, v.y, o);
            v.z += __shfl_xor_sync(0xffffffffu, v.z, o);
            v.w += __shfl_xor_sync(0xffffffffu, v.w, o);
        }
        if ((threadIdx.x & 31) == 0)
            red4(sb + (size_t)idx * C_ + c, v);
    } else {
        red4(sb + (size_t)idx * C_ + c, v);
    }
}

__global__ __launch_bounds__(224)
void k_scatter(const float* __restrict__ feat,
               const float* __restrict__ depth,
               const float* __restrict__ I_inv,
               const float* __restrict__ E_inv,
               const float* __restrict__ Vm) {
    const int p  = blockIdx.x * blockDim.x + threadIdx.x;   // 100*224 == 22400 exact
    const int bn = blockIdx.y;

    // ---- geometry (bug-faithful: grid flattened width-outer) ----
    const float u = (float)(p / HF_);     // image x (width index)
    const float v = (float)(p % HF_);     // image y (height index)

    const float* Ii = I_inv + bn * 9;
    const float* Ei = E_inv + bn * 16;

    const float cx = Ii[0] * u + Ii[1] * v + Ii[2];
    const float cy = Ii[3] * u + Ii[4] * v + Ii[5];
    const float cz = Ii[6] * u + Ii[7] * v + Ii[8];

    const float tx = Ei[3], ty = Ei[7], tz = Ei[11];
    // reference keeps the +t in the "direction" (d = E_inv @ [cam;1])
    const float dx = Ei[0] * cx + Ei[1] * cy + Ei[2]  * cz + tx;
    const float dy = Ei[4] * cx + Ei[5] * cy + Ei[6]  * cz + ty;
    const float dz = Ei[8] * cx + Ei[9] * cy + Ei[10] * cz + tz;

    const float s = -tz / fmaxf(dz, 1e-6f);
    const float ex = tx + dx * s;
    const float ey = ty + dy * s;

    const float p0 = Vm[0] * ex + Vm[1] * ey + Vm[2];
    const float p1 = Vm[3] * ex + Vm[4] * ey + Vm[5];
    const float p2 = Vm[6] * ex + Vm[7] * ey + Vm[8];
    const float zc = fmaxf(p2, 1e-7f);
    const float bevx = p0 / zc;
    const float bevy = p1 / zc;

    // gx/px round-trip (replicate reference float ops)
    const float gx = bevx / (float)(BEVW - 1) * 2.f - 1.f;
    const float gy = bevy / (float)(BEVH - 1) * 2.f - 1.f;
    const float px = (gx + 1.f) * (float)(BEVW - 1) / 2.f;
    const float py = (gy + 1.f) * (float)(BEVH - 1) / 2.f;

    const float x0 = fminf(fmaxf(floorf(px), 0.f), (float)(BEVW - 1));
    const float y0 = fminf(fmaxf(floorf(py), 0.f), (float)(BEVH - 1));
    const float x1 = fminf(x0 + 1.f, (float)(BEVW - 1));
    const float y1 = fminf(y0 + 1.f, (float)(BEVH - 1));

    // ---- conf = max_d depth_prob[bn, d, p] ----
    const float* dp = depth + (size_t)bn * D_ * HWP + p;
    float conf = dp[0];
    #pragma unroll 8
    for (int d = 1; d < D_; d++)
        conf = fmaxf(conf, dp[(size_t)d * HWP]);

    const float scale = conf * (1.f / (float)N_);   // fold mean over n

    const float w00 = (x1 - px) * (y1 - py) * scale;
    const float w10 = (px - x0) * (y1 - py) * scale;
    const float w01 = (x1 - px) * (py - y0) * scale;
    const float w11 = (px - x0) * (py - y0) * scale;

    const int i00 = (int)y0 * BEVW + (int)x0;
    const int i10 = (int)y0 * BEVW + (int)x1;
    const int i01 = (int)y1 * BEVW + (int)x0;
    const int i11 = (int)y1 * BEVW + (int)x1;

    // per-corner warp-uniformity vote (hot border cells -> warp aggregation)
    const unsigned FULL = 0xffffffffu;
    const int l0_00 = __shfl_sync(FULL, i00, 0);
    const int l0_10 = __shfl_sync(FULL, i10, 0);
    const int l0_01 = __shfl_sync(FULL, i01, 0);
    const int l0_11 = __shfl_sync(FULL, i11, 0);
    const bool u00 = __all_sync(FULL, i00 == l0_00);
    const bool u10 = __all_sync(FULL, i10 == l0_10);
    const bool u01 = __all_sync(FULL, i01 == l0_01);
    const bool u11 = __all_sync(FULL, i11 == l0_11);

    float* sb = g_scratch + (size_t)(bn / N_) * HWB * C_;
    const float* fp = feat + (size_t)bn * C_ * HWP + p;

    #pragma unroll 4
    for (int c = 0; c < C_; c += 4) {
        float4 f;
        f.x = __ldg(fp + (size_t)(c + 0) * HWP);
        f.y = __ldg(fp + (size_t)(c + 1) * HWP);
        f.z = __ldg(fp + (size_t)(c + 2) * HWP);
        f.w = __ldg(fp + (size_t)(c + 3) * HWP);
        emit(sb, i00, u00, w00, f, c);
        emit(sb, i10, u10, w10, f, c);
        emit(sb, i01, u01, w01, f, c);
        emit(sb, i11, u11, w11, f, c);
    }
}

// scratch [b][cell][c] -> out [b][c][cell], tiled transpose
__global__ __launch_bounds__(256)
void k_transpose(float* __restrict__ out) {
    __shared__ float tile[32][33];
    const int cellBase = blockIdx.x * 32;   // 40000 / 32 = 1250 exact
    const int cBase    = blockIdx.y * 32;   // 64 / 32 = 2
    const int b        = blockIdx.z;
    const int tx = threadIdx.x;             // 0..31
    const int ty = threadIdx.y;             // 0..7

    const float* src = g_scratch + (size_t)b * HWB * C_;
    #pragma unroll
    for (int r = 0; r < 4; r++) {
        int cell = cellBase + ty + r * 8;
        tile[ty + r * 8][tx] = src[(size_t)cell * C_ + cBase + tx];
    }
    __syncthreads();
    #pragma unroll
    for (int r = 0; r < 4; r++) {
        int ch = cBase + ty + r * 8;
        out[((size_t)b * C_ + ch) * HWB + cellBase + tx] = tile[tx][ty + r * 8];
    }
}

extern "C" void kernel_launch(void* const* d_in, const int* in_sizes, int n_in,
                              void* d_out, int out_size) {
    const float* feat  = (const float*)d_in[0];
    const float* depth = (const float*)d_in[1];
    const float* I_inv = (const float*)d_in[2];
    const float* E_inv = (const float*)d_in[3];
    const float* Vm    = (const float*)d_in[4];
    float* out = (float*)d_out;

    k_zero<<<2560, 512>>>();

    dim3 gs(HWP / 224, B_ * N_);   // (100, 12)
    k_scatter<<<gs, 224>>>(feat, depth, I_inv, E_inv, Vm);

    dim3 gt(HWB / 32, C_ / 32, B_);  // (1250, 2, 2)
    dim3 bt(32, 8);
    k_transpose<<<gt, bt>>>(out);
}

// round 8
// speedup vs baseline: 5.9819x; 5.9819x over previous
#include <cuda_runtime.h>

// LiftSplatBEV — fixed shapes
// feat_bn   : [12, 64, 112, 200] f32
// depth_prob: [12, 64, 112, 200] f32
// I_inv     : [2, 6, 3, 3] f32
// E_inv     : [2, 6, 4, 4] f32
// V         : [3, 3] f32
// out       : [2, 64, 200, 200] f32

static constexpr int B_   = 2;
static constexpr int N_   = 6;
static constexpr int C_   = 64;
static constexpr int HF_  = 112;
static constexpr int WF_  = 200;
static constexpr int D_   = 64;
static constexpr int HWP  = HF_ * WF_;     // 22400
static constexpr int BEVH = 200;
static constexpr int BEVW = 200;
static constexpr int HWB  = BEVH * BEVW;   // 40000

// Accumulator scratch: [b][bev_cell][channel]  (channel contiguous -> v4 atomics)
__device__ float g_scratch[(size_t)B_ * HWB * C_];

__global__ void k_zero() {
    const int n4 = (B_ * HWB * C_) / 4;
    float4 z = make_float4(0.f, 0.f, 0.f, 0.f);
    float4* p = reinterpret_cast<float4*>(g_scratch);
    for (int i = blockIdx.x * blockDim.x + threadIdx.x; i < n4;
         i += gridDim.x * blockDim.x)
        p[i] = z;
}

__device__ __forceinline__ void red4(float* a, float4 v) {
    asm volatile("red.global.add.v4.f32 [%0], {%1,%2,%3,%4};"
                 :: "l"(a), "f"(v.x), "f"(v.y), "f"(v.z), "f"(v.w)
                 : "memory");
}

__global__ __launch_bounds__(224)
void k_scatter(const float* __restrict__ feat,
               const float* __restrict__ depth,
               const float* __restrict__ I_inv,
               const float* __restrict__ E_inv,
               const float* __restrict__ Vm) {
    const int p    = blockIdx.x * blockDim.x + threadIdx.x;   // 100*224 == 22400
    const int bn   = blockIdx.y;
    const int lane = threadIdx.x & 31;
    const unsigned FULL = 0xffffffffu;

    // ---- geometry (bug-faithful: grid flattened width-outer) ----
    const float u = (float)(p / HF_);     // image x (width index)
    const float v = (float)(p % HF_);     // image y (height index)

    const float* Ii = I_inv + bn * 9;
    const float* Ei = E_inv + bn * 16;

    const float cx = Ii[0] * u + Ii[1] * v + Ii[2];
    const float cy = Ii[3] * u + Ii[4] * v + Ii[5];
    const float cz = Ii[6] * u + Ii[7] * v + Ii[8];

    const float tx = Ei[3], ty = Ei[7], tz = Ei[11];
    // reference keeps the +t in the "direction" (d = E_inv @ [cam;1])
    const float dx = Ei[0] * cx + Ei[1] * cy + Ei[2]  * cz + tx;
    const float dy = Ei[4] * cx + Ei[5] * cy + Ei[6]  * cz + ty;
    const float dz = Ei[8] * cx + Ei[9] * cy + Ei[10] * cz + tz;

    const float s  = -tz / fmaxf(dz, 1e-6f);
    const float ex = tx + dx * s;
    const float ey = ty + dy * s;

    const float p0 = Vm[0] * ex + Vm[1] * ey + Vm[2];
    const float p1 = Vm[3] * ex + Vm[4] * ey + Vm[5];
    const float p2 = Vm[6] * ex + Vm[7] * ey + Vm[8];
    const float zc = fmaxf(p2, 1e-7f);
    const float bevx = p0 / zc;
    const float bevy = p1 / zc;

    // gx/px round-trip (replicate reference float ops)
    const float gx = bevx / (float)(BEVW - 1) * 2.f - 1.f;
    const float gy = bevy / (float)(BEVH - 1) * 2.f - 1.f;
    const float px = (gx + 1.f) * (float)(BEVW - 1) / 2.f;
    const float py = (gy + 1.f) * (float)(BEVH - 1) / 2.f;

    const float x0 = fminf(fmaxf(floorf(px), 0.f), (float)(BEVW - 1));
    const float y0 = fminf(fmaxf(floorf(py), 0.f), (float)(BEVH - 1));
    const float x1 = fminf(x0 + 1.f, (float)(BEVW - 1));
    const float y1 = fminf(y0 + 1.f, (float)(BEVH - 1));

    // ---- conf = max_d depth_prob[bn, d, p] ----
    const float* dp = depth + (size_t)bn * D_ * HWP + p;
    float conf = dp[0];
    #pragma unroll 8
    for (int d = 1; d < D_; d++)
        conf = fmaxf(conf, dp[(size_t)d * HWP]);

    const float scale = conf * (1.f / (float)N_);   // fold mean over n

    float ws[4];
    ws[0] = (x1 - px) * (y1 - py) * scale;
    ws[1] = (px - x0) * (y1 - py) * scale;
    ws[2] = (x1 - px) * (py - y0) * scale;
    ws[3] = (px - x0) * (py - y0) * scale;

    int idxs[4];
    idxs[0] = (int)y0 * BEVW + (int)x0;
    idxs[1] = (int)y0 * BEVW + (int)x1;
    idxs[2] = (int)y1 * BEVW + (int)x0;
    idxs[3] = (int)y1 * BEVW + (int)x1;

    // ---- per-corner segmented-run structure ----
    // Segments are defined ONLY by head flags (head = id differs from lane-1),
    // so they are contiguous by construction (A,B,A -> 3 singleton segments).
    // cond[k] bit st: legal to fold in lane+2^st (same segment, in warp).
    // step[k] bit st: warp-uniform "any lane needs step st" (skip whole steps).
    unsigned cond[4];
    bool     head[4];
    unsigned step[4];
    #pragma unroll
    for (int k = 0; k < 4; k++) {
        const int id = idxs[k];
        const int up = __shfl_up_sync(FULL, id, 1);
        const bool h = (lane == 0) || (up != id);
        head[k] = h;
        const unsigned hbm = __ballot_sync(FULL, h);
        const unsigned long long above = (unsigned long long)hbm >> (lane + 1);
        unsigned cm = 0;
        #pragma unroll
        for (int st = 0; st < 5; st++) {
            const int off = 1 << st;
            if ((lane + off < 32) &&
                ((above & (unsigned long long)((1u << off) - 1u)) == 0ull))
                cm |= (1u << st);
        }
        cond[k] = cm;
        unsigned sm = 0;
        #pragma unroll
        for (int st = 0; st < 5; st++)
            if (__any_sync(FULL, cm & (1u << st))) sm |= (1u << st);
        step[k] = sm;
    }

    float* sb = g_scratch + (size_t)(bn / N_) * HWB * C_;
    const float* fp = feat + (size_t)bn * C_ * HWP + p;

    #pragma unroll 2
    for (int c = 0; c < C_; c += 4) {
        float4 f;
        f.x = __ldg(fp + (size_t)(c + 0) * HWP);
        f.y = __ldg(fp + (size_t)(c + 1) * HWP);
        f.z = __ldg(fp + (size_t)(c + 2) * HWP);
        f.w = __ldg(fp + (size_t)(c + 3) * HWP);

        #pragma unroll
        for (int k = 0; k < 4; k++) {
            float4 vv = make_float4(f.x * ws[k], f.y * ws[k],
                                    f.z * ws[k], f.w * ws[k]);
            if (step[k]) {
                // segmented suffix-sum: head lane ends with its segment total
                #pragma unroll
                for (int st = 0; st < 5; st++) {
                    if (step[k] & (1u << st)) {   // warp-uniform
                        const int off = 1 << st;
                        float ox = __shfl_down_sync(FULL, vv.x, off);
                        float oy = __shfl_down_sync(FULL, vv.y, off);
                        float oz = __shfl_down_sync(FULL, vv.z, off);
                        float ow = __shfl_down_sync(FULL, vv.w, off);
                        if (cond[k] & (1u << st)) {
                            vv.x += ox; vv.y += oy; vv.z += oz; vv.w += ow;
                        }
                    }
                }
                if (head[k])
                    red4(sb + (size_t)idxs[k] * C_ + c, vv);
            } else {
                red4(sb + (size_t)idxs[k] * C_ + c, vv);
            }
        }
    }
}

// scratch [b][cell][c] -> out [b][c][cell], tiled transpose
__global__ __launch_bounds__(256)
void k_transpose(float* __restrict__ out) {
    __shared__ float tile[32][33];
    const int cellBase = blockIdx.x * 32;   // 40000 / 32 = 1250 exact
    const int cBase    = blockIdx.y * 32;   // 64 / 32 = 2
    const int b        = blockIdx.z;
    const int tx = threadIdx.x;             // 0..31
    const int ty = threadIdx.y;             // 0..7

    const float* src = g_scratch + (size_t)b * HWB * C_;
    #pragma unroll
    for (int r = 0; r < 4; r++) {
        int cell = cellBase + ty + r * 8;
        tile[ty + r * 8][tx] = src[(size_t)cell * C_ + cBase + tx];
    }
    __syncthreads();
    #pragma unroll
    for (int r = 0; r < 4; r++) {
        int ch = cBase + ty + r * 8;
        out[((size_t)b * C_ + ch) * HWB + cellBase + tx] = tile[tx][ty + r * 8];
    }
}

extern "C" void kernel_launch(void* const* d_in, const int* in_sizes, int n_in,
                              void* d_out, int out_size) {
    const float* feat  = (const float*)d_in[0];
    const float* depth = (const float*)d_in[1];
    const float* I_inv = (const float*)d_in[2];
    const float* E_inv = (const float*)d_in[3];
    const float* Vm    = (const float*)d_in[4];
    float* out = (float*)d_out;

    k_zero<<<2560, 512>>>();

    dim3 gs(HWP / 224, B_ * N_);   // (100, 12)
    k_scatter<<<gs, 224>>>(feat, depth, I_inv, E_inv, Vm);

    dim3 gt(HWB / 32, C_ / 32, B_);  // (1250, 2, 2)
    dim3 bt(32, 8);
    k_transpose<<<gt, bt>>>(out);
}